// round 13
// baseline (speedup 1.0000x reference)
// R13: byte-equivalent resubmission of the R12 kernel (BK=64 + fused atomic
// combine). R12 failed with "GB300 container failed twice" — same infra-flake
// signature as R5 and R10, both of which passed on identical resubmit.
// Kernel-side hang surface audit: block-uniform __syncthreads only, no
// mbarrier waits, 64 MB statics, 72.7 KB smem, atomicAdd cannot deadlock.
#include <cuda_runtime.h>
#include <cuda_fp16.h>

#define T    4096
#define DIM  1024
#define HID  4096
#define E    8
#define KTOP 2
#define NROW (T * KTOP)

#define BM 128
#define BN 128
#define BK 64
#define MT 32            // max M-tiles per expert
#define NTHR 512         // 16 warps: 4 (m) x 4 (n), warp tile 32x32

// SMEM per stage: A[128][72h] (64 data + 8 pad), B[64][136h] (128 data + 8 pad)
#define PITCH_A  144             // bytes: 72 halves
#define PITCH_B  272             // bytes: 136 halves
#define PL_A     (128 * PITCH_A) // 18432
#define PL_B     (64 * PITCH_B)  // 17408
#define OFF_A    0
#define OFF_B    PL_A
#define STAGE_B  (PL_A + PL_B)           // 35840
#define GEMM_SMEM (1024 + 2 * STAGE_B)   // 72704

// ---------------- static scratch (64 MB total) -------------------------------
__device__ int   g_counts[E];
__device__ int   g_fill[E];
__device__ int   g_offsets[E + 1];
__device__ int   g_topk_e[T * KTOP];
__device__ float g_topk_p[T * KTOP];
__device__ int   g_row_token[NROW];
__device__ float g_row_p[NROW];

__device__ __half g_H[(size_t)NROW * HID];     // 64 MB

// ---------------- PTX helpers ------------------------------------------------
__device__ __forceinline__ unsigned smem_u32(const void* p) {
    unsigned a;
    asm("{ .reg .u64 t; cvta.to.shared.u64 t, %1; cvt.u32.u64 %0, t; }" : "=r"(a) : "l"(p));
    return a;
}
__device__ __forceinline__ void ldsm4(unsigned* r, unsigned addr) {
    asm volatile("ldmatrix.sync.aligned.m8n8.x4.shared.b16 {%0,%1,%2,%3}, [%4];"
                 : "=r"(r[0]), "=r"(r[1]), "=r"(r[2]), "=r"(r[3]) : "r"(addr));
}
__device__ __forceinline__ void ldsm4t(unsigned* r, unsigned addr) {
    asm volatile("ldmatrix.sync.aligned.m8n8.x4.trans.shared.b16 {%0,%1,%2,%3}, [%4];"
                 : "=r"(r[0]), "=r"(r[1]), "=r"(r[2]), "=r"(r[3]) : "r"(addr));
}
__device__ __forceinline__ void mma16816(float* c, const unsigned* a, const unsigned* b) {
    asm volatile(
        "mma.sync.aligned.m16n8k16.row.col.f32.f16.f16.f32 "
        "{%0,%1,%2,%3}, {%4,%5,%6,%7}, {%8,%9}, {%0,%1,%2,%3};"
        : "+f"(c[0]), "+f"(c[1]), "+f"(c[2]), "+f"(c[3])
        : "r"(a[0]), "r"(a[1]), "r"(a[2]), "r"(a[3]), "r"(b[0]), "r"(b[1]));
}
__device__ __forceinline__ unsigned pack2h(float a, float b) {
    __half2 H = __halves2half2(__float2half_rn(a), __float2half_rn(b));
    return *(unsigned*)&H;
}

// ---------------- init -------------------------------------------------------
__global__ void init_kernel() {
    int i = threadIdx.x;
    if (i < E) { g_counts[i] = 0; g_fill[i] = 0; }
}

__global__ void zero_out_kernel(float* __restrict__ out) {
    size_t i = ((size_t)blockIdx.x * blockDim.x + threadIdx.x) * 4;
    float4 z; z.x = 0.f; z.y = 0.f; z.z = 0.f; z.w = 0.f;
    *(float4*)(out + i) = z;
}

// ---------------- gating (exact fp32; one warp per token) --------------------
__global__ void gating_kernel(const float* __restrict__ x,
                              const float* __restrict__ gw,
                              const float* __restrict__ gb) {
    int warp = (blockIdx.x * blockDim.x + threadIdx.x) >> 5;
    int lane = threadIdx.x & 31;
    if (warp >= T) return;
    const float* xr = x + (size_t)warp * DIM;

    float acc[E];
#pragma unroll
    for (int e = 0; e < E; e++) acc[e] = 0.f;
    for (int d = lane; d < DIM; d += 32) {
        float xv = xr[d];
        float4 g0 = *(const float4*)(gw + d * E);
        float4 g1 = *(const float4*)(gw + d * E + 4);
        acc[0] += xv * g0.x; acc[1] += xv * g0.y;
        acc[2] += xv * g0.z; acc[3] += xv * g0.w;
        acc[4] += xv * g1.x; acc[5] += xv * g1.y;
        acc[6] += xv * g1.z; acc[7] += xv * g1.w;
    }
#pragma unroll
    for (int e = 0; e < E; e++)
#pragma unroll
        for (int off = 16; off > 0; off >>= 1)
            acc[e] += __shfl_down_sync(0xffffffffu, acc[e], off);

    if (lane == 0) {
        float lg[E];
        float m = -1e30f;
#pragma unroll
        for (int e = 0; e < E; e++) { lg[e] = acc[e] + gb[e]; m = fmaxf(m, lg[e]); }
        float s = 0.f;
#pragma unroll
        for (int e = 0; e < E; e++) { lg[e] = expf(lg[e] - m); s += lg[e]; }
        int e1 = 0;
#pragma unroll
        for (int e = 1; e < E; e++) if (lg[e] > lg[e1]) e1 = e;
        int e2 = (e1 == 0) ? 1 : 0;
#pragma unroll
        for (int e = 0; e < E; e++) if (e != e1 && e != e2 && lg[e] > lg[e2]) e2 = e;
        float inv = 1.0f / s;
        g_topk_e[warp * 2 + 0] = e1;
        g_topk_e[warp * 2 + 1] = e2;
        g_topk_p[warp * 2 + 0] = lg[e1] * inv;
        g_topk_p[warp * 2 + 1] = lg[e2] * inv;
        atomicAdd(&g_counts[e1], 1);
        atomicAdd(&g_counts[e2], 1);
    }
}

__global__ void scan_kernel() {
    if (threadIdx.x == 0) {
        int acc = 0;
        g_offsets[0] = 0;
        for (int e = 0; e < E; e++) { acc += g_counts[e]; g_offsets[e + 1] = acc; }
    }
}

__global__ void assign_kernel() {
    int t = blockIdx.x * blockDim.x + threadIdx.x;
    if (t >= T) return;
#pragma unroll
    for (int k = 0; k < KTOP; k++) {
        int e = g_topk_e[t * 2 + k];
        int slot = atomicAdd(&g_fill[e], 1);
        int row = g_offsets[e] + slot;
        g_row_token[row] = t;
        g_row_p[row] = g_topk_p[t * 2 + k];
    }
}

// ---------------- grouped HMMA GEMM (fp16 x fp16, fp32 acc), BK=64 -----------
// G1: C[rows,HID] = gather(x)@w1, +b1, ReLU -> g_H (fp16)
// G2: out[tok] += p * (H@w2 + b2)  (atomicAdd; 2 addends -> deterministic)
// Stage LDG/STS split into two halves interleaved with the two compute halves,
// keeping register staging at the BK=32 level while halving sync count.
template <int KD, int NTOT, bool G1>
__global__ void __launch_bounds__(NTHR, 1)
moe_gemm(const float* __restrict__ xA,
         const float* __restrict__ wB,    // [E][KD][NTOT] fp32 (k-major rows)
         const float* __restrict__ bias,
         float* __restrict__ outp) {
    int e  = blockIdx.y >> 5;
    int mt = blockIdx.y & 31;
    int cnt = g_counts[e];
    int m0 = mt * BM;
    if (m0 >= cnt) return;
    int n0 = blockIdx.x * BN;
    int base = g_offsets[e];

    extern __shared__ char smem[];
    int* toks = (int*)smem;
    char* tiles = smem + 1024;

    int tid  = threadIdx.x;
    int lane = tid & 31;
    int wid  = tid >> 5;

    if (G1 && tid < BM) {
        int m = m0 + tid;
        toks[tid] = g_row_token[base + (m < cnt ? m : cnt - 1)];
    }
    __syncthreads();

    // ---- load mapping: A: 4 threads/row, 16 elts each; B: 8 threads/k-row, 16 cols each
    int arow = tid >> 2, kh = (tid & 3) * 16;
    int brow = tid >> 3, nh = (tid & 7) * 16;

    const float* aF = nullptr;
    const __half* aH = nullptr;
    if (G1) {
        aF = xA + (size_t)toks[arow] * KD + kh;
    } else {
        int m = m0 + arow; if (m >= cnt) m = cnt - 1;
        aH = g_H + (size_t)(base + m) * KD + kh;
    }
    const float* bF = wB + ((size_t)e * KD + brow) * NTOT + n0 + nh;

    unsigned aoff = (unsigned)(arow * PITCH_A + kh * 2);
    unsigned boff = (unsigned)(brow * PITCH_B + nh * 2);

    // ---- staged registers (one half at a time: 8 A + 8 B)
    float fa[8];
    uint4 ha;
    float fb[8];

    auto ldg_half = [&](int c, int h) {
        int kk = c * BK;
        if (G1) {
            *(float4*)(fa)     = __ldg((const float4*)(aF + kk + h * 8));
            *(float4*)(fa + 4) = __ldg((const float4*)(aF + kk + h * 8 + 4));
        } else {
            ha = __ldg((const uint4*)(aH + kk + h * 8));
        }
        const float* bp = bF + (size_t)kk * NTOT + h * 8;
        *(float4*)(fb)     = __ldg((const float4*)(bp));
        *(float4*)(fb + 4) = __ldg((const float4*)(bp + 4));
    };

    auto sts_half = [&](int st, int h) {
        char* stb = tiles + st * STAGE_B;
        if (G1) {
            unsigned hh[4];
#pragma unroll
            for (int q = 0; q < 4; q++) hh[q] = pack2h(fa[2 * q], fa[2 * q + 1]);
            *(uint4*)(stb + OFF_A + aoff + h * 16) = make_uint4(hh[0], hh[1], hh[2], hh[3]);
        } else {
            *(uint4*)(stb + OFF_A + aoff + h * 16) = ha;
        }
        unsigned hh[4];
#pragma unroll
        for (int q = 0; q < 4; q++) hh[q] = pack2h(fb[2 * q], fb[2 * q + 1]);
        *(uint4*)(stb + OFF_B + boff + h * 16) = make_uint4(hh[0], hh[1], hh[2], hh[3]);
    };

    // ---- compute mapping: warp (wm, wn) owns 32x32
    int wm = wid >> 2;     // 0..3
    int wn = wid & 3;      // 0..3
    unsigned sbase = smem_u32(tiles);
    unsigned a_off = (unsigned)((wm * 32 + (lane & 15)) * PITCH_A + (lane >> 4) * 16);
    unsigned b_off = (unsigned)((lane & 15) * PITCH_B + (wn * 32 + (lane >> 4) * 8) * 2);

    float acc[2][4][4];
#pragma unroll
    for (int i = 0; i < 2; i++)
#pragma unroll
        for (int j = 0; j < 4; j++)
#pragma unroll
            for (int q = 0; q < 4; q++) acc[i][j][q] = 0.f;

    auto compute_ks = [&](unsigned stb, int ks) {
        unsigned afr[2][4], bfr[4][2];
#pragma unroll
        for (int i = 0; i < 2; i++) {
            unsigned ad = stb + a_off + (unsigned)(i * 16 * PITCH_A) + (unsigned)(ks * 32);
            ldsm4(afr[i], ad + OFF_A);
        }
#pragma unroll
        for (int jj = 0; jj < 2; jj++) {
            unsigned bd = stb + b_off + (unsigned)(ks * 16 * PITCH_B) + (unsigned)(jj * 32);
            unsigned th[4];
            ldsm4t(th, bd + OFF_B);
            bfr[2 * jj][0] = th[0]; bfr[2 * jj][1] = th[1];
            bfr[2 * jj + 1][0] = th[2]; bfr[2 * jj + 1][1] = th[3];
        }
#pragma unroll
        for (int i = 0; i < 2; i++)
#pragma unroll
            for (int j = 0; j < 4; j++)
                mma16816(acc[i][j], afr[i], bfr[j]);
    };

    const int NC = KD / BK;
    ldg_half(0, 0); sts_half(0, 0);
    ldg_half(0, 1); sts_half(0, 1);
    __syncthreads();
    for (int c = 0; c < NC; c++) {
        int st = c & 1, nst = (c + 1) & 1;
        unsigned stb = sbase + st * STAGE_B;
        bool more = (c + 1 < NC);
        if (more) ldg_half(c + 1, 0);
        compute_ks(stb, 0);
        compute_ks(stb, 1);
        if (more) { sts_half(nst, 0); ldg_half(c + 1, 1); }
        compute_ks(stb, 2);
        compute_ks(stb, 3);
        if (more) sts_half(nst, 1);
        __syncthreads();
    }

    // ---- epilogue
    int r_base = wm * 32 + (lane >> 2);
    int c_base = n0 + wn * 32 + 2 * (lane & 3);
#pragma unroll
    for (int i = 0; i < 2; i++) {
#pragma unroll
        for (int h = 0; h < 2; h++) {
            int m = m0 + r_base + i * 16 + h * 8;
            if (m >= cnt) continue;
            size_t orow = (size_t)(base + m);
            int tok = 0; float p = 0.f;
            if (!G1) { tok = g_row_token[orow]; p = g_row_p[orow]; }
#pragma unroll
            for (int j = 0; j < 4; j++) {
                int n = c_base + j * 8;
                float v0 = acc[i][j][h * 2];
                float v1 = acc[i][j][h * 2 + 1];
                if (G1) {
                    v0 += __ldg(&bias[(size_t)e * NTOT + n]);
                    v1 += __ldg(&bias[(size_t)e * NTOT + n + 1]);
                    v0 = fmaxf(v0, 0.f); v1 = fmaxf(v1, 0.f);
                    *(unsigned*)(g_H + orow * HID + n) = pack2h(v0, v1);
                } else {
                    v0 = p * (v0 + __ldg(&bias[(size_t)e * NTOT + n]));
                    v1 = p * (v1 + __ldg(&bias[(size_t)e * NTOT + n + 1]));
                    atomicAdd(outp + (size_t)tok * DIM + n, v0);
                    atomicAdd(outp + (size_t)tok * DIM + n + 1, v1);
                }
            }
        }
    }
}

// ---------------- launch -----------------------------------------------------
extern "C" void kernel_launch(void* const* d_in, const int* in_sizes, int n_in,
                              void* d_out, int out_size) {
    (void)in_sizes; (void)n_in; (void)out_size;
    const float* x  = (const float*)d_in[0];
    const float* gw = (const float*)d_in[1];
    const float* gb = (const float*)d_in[2];
    const float* w1 = (const float*)d_in[3];
    const float* b1 = (const float*)d_in[4];
    const float* w2 = (const float*)d_in[5];
    const float* b2 = (const float*)d_in[6];
    float* out = (float*)d_out;

    cudaFuncSetAttribute((const void*)moe_gemm<DIM, HID, true>,
                         cudaFuncAttributeMaxDynamicSharedMemorySize, GEMM_SMEM);
    cudaFuncSetAttribute((const void*)moe_gemm<HID, DIM, false>,
                         cudaFuncAttributeMaxDynamicSharedMemorySize, GEMM_SMEM);

    init_kernel<<<1, 32>>>();
    gating_kernel<<<T / 8, 256>>>(x, gw, gb);
    scan_kernel<<<1, 32>>>();
    assign_kernel<<<T / 256, 256>>>();
    zero_out_kernel<<<(T * DIM) / (256 * 4), 256>>>(out);

    moe_gemm<DIM, HID, true><<<dim3(HID / BN, E * MT), NTHR, GEMM_SMEM>>>(x, w1, b1, nullptr);
    moe_gemm<HID, DIM, false><<<dim3(DIM / BN, E * MT), NTHR, GEMM_SMEM>>>(x, w2, b2, out);
}